// round 13
// baseline (speedup 1.0000x reference)
#include <cuda_runtime.h>
#include <math.h>

#define NN 80
#define PAIRS (NN * NN)          // 6400
#define MAX_ITERS 60
#define TOL 1e-3f
#define TPB 256

__global__ void zero_out(float* __restrict__ out) {
    out[threadIdx.x] = 0.0f;     // d_out is poisoned; we accumulate atomically
}

__global__ __launch_bounds__(TPB, 4)
void power_iter_kernel(const float* __restrict__ r_zeros,
                       const float* __restrict__ r_const,
                       const float* __restrict__ t_paths,
                       const float* __restrict__ weights_t,
                       const float* __restrict__ weights_r,
                       float* __restrict__ out) {
    __shared__ __align__(8) float wbuf[2][NN];  // ping-pong: w = A v (unnorm.)
    __shared__ float red_ww[8];    // per-warp partials of w.w
    __shared__ float red_vw[8];    // per-warp partials of v.(Av)
    __shared__ float s_n2;         // broadcast: ||w_out||^2
    __shared__ float s_ev;         // broadcast: v_in . out

    const int p    = blockIdx.x;
    const int tid  = threadIdx.x;
    const int warp = tid >> 5;
    const int lane = tid & 31;
    const bool hi  = (lane & 16) != 0;

    // ---- Build A = weights_r * r_zeros + r_const DIRECTLY INTO REGISTERS.
    // Warp w owns rows {w, w+8, ..., w+72}. Lane holds cols {2*lane, 2*lane+1}
    // as one float2 (coalesced LDG.64: warp covers 256B contiguous) plus the
    // tail col 64+lane for lane<16 (scalar). Streaming hint (read-once).
    const size_t base = (size_t)p * (NN * NN);
    const float* __restrict__ rz = r_zeros   + base;
    const float* __restrict__ rc = r_const   + base;
    const float* __restrict__ wr = weights_r + base;

    float2 a01[10];
    float  a2[10];
    #pragma unroll
    for (int r = 0; r < 10; ++r) {
        const int row = warp + (r << 3);
        const int o0  = row * NN + (lane << 1);        // 8B-aligned
        const float2 wa = __ldcs((const float2*)(wr + o0));
        const float2 zb = __ldcs((const float2*)(rz + o0));
        const float2 cb = __ldcs((const float2*)(rc + o0));
        a01[r].x = fmaf(wa.x, zb.x, cb.x);
        a01[r].y = fmaf(wa.y, zb.y, cb.y);
        a2[r] = 0.0f;
        if (lane < 16) {
            const int o2 = row * NN + 64 + lane;
            a2[r] = fmaf(__ldcs(wr + o2), __ldcs(rz + o2), __ldcs(rc + o2));
        }
    }

    if (tid < NN) wbuf[0][tid] = 0.11180339887498949f;  // v0 = 1/sqrt(80)
    __syncthreads();

    // mv: v_in = in*inv; out = A v_in; s_n2 = out.out; s_ev = v_in.out.
    // Pair-folded row reduce (R10-proven): 6 SHFL per 2 rows.
    auto mv = [&](const float* in, float* outb, float inv) {
        const float2 vin = ((const float2*)in)[lane];       // cols 2L, 2L+1
        const float vx = vin.x * inv;
        const float vy = vin.y * inv;
        const float vt = (lane < 16) ? in[64 + lane] * inv : 0.0f;
        float ww = 0.0f, vwacc = 0.0f;
        #pragma unroll
        for (int k = 0; k < 5; ++k) {
            const int rA = warp + (k << 4);       // row for r=2k
            const int rB = rA + 8;                // row for r=2k+1
            float sA = a01[2*k].x * vx;
            sA = fmaf(a01[2*k].y,   vy, sA);
            sA = fmaf(a2[2*k],      vt, sA);
            float sB = a01[2*k+1].x * vx;
            sB = fmaf(a01[2*k+1].y, vy, sB);
            sB = fmaf(a2[2*k+1],    vt, sB);
            sA += __shfl_xor_sync(0xFFFFFFFFu, sA, 16);
            sB += __shfl_xor_sync(0xFFFFFFFFu, sB, 16);
            float u = hi ? sB : sA;               // 0-15: rowA, 16-31: rowB
            u += __shfl_xor_sync(0xFFFFFFFFu, u, 8);
            u += __shfl_xor_sync(0xFFFFFFFFu, u, 4);
            u += __shfl_xor_sync(0xFFFFFFFFu, u, 2);
            u += __shfl_xor_sync(0xFFFFFFFFu, u, 1);
            if ((lane & 15) == 0) {               // leaders: lane 0 & lane 16
                const int row = hi ? rB : rA;
                outb[row] = u;
                ww    = fmaf(u, u, ww);
                vwacc = fmaf(in[row] * inv, u, vwacc);
            }
        }
        ww    += __shfl_xor_sync(0xFFFFFFFFu, ww,    16);
        vwacc += __shfl_xor_sync(0xFFFFFFFFu, vwacc, 16);
        if (lane == 0) { red_ww[warp] = ww; red_vw[warp] = vwacc; }
        __syncthreads();
        if (tid == 0) {
            float A = 0.0f, B = 0.0f;
            #pragma unroll
            for (int k = 0; k < 8; ++k) { A += red_ww[k]; B += red_vw[k]; }
            s_n2 = A; s_ev = B;
        }
        __syncthreads();
    };

    // ---- mv#0: in = v0 (inv=1): ev0 = v0.(A v0), wbuf[1] = A v0
    mv(wbuf[0], wbuf[1], 1.0f);
    float ev = s_ev;

    // ---- iterate: v_{k+1} = w_k/||w_k||; ev_{k+1} = v_{k+1}.(A v_{k+1})
    int bin = 1;
    float inv_last = 1.0f;
    for (int it = 0; it < MAX_ITERS; ++it) {
        const float inv = 1.0f / sqrtf(s_n2);     // uniform per-thread scalar
        mv(wbuf[bin], wbuf[bin ^ 1], inv);        // reads w*inv, writes A v_new
        inv_last = inv;
        const float ev_new = s_ev;
        if (fabsf(ev - ev_new) < TOL) break;      // v_final = wbuf[bin]*inv
        ev = ev_new;
        bin ^= 1;
    }

    // ---- out[i] += v_final[i] * (T[p] / v_final[src]),  src = p / n
    if (tid < NN) {
        const float tval = weights_t[p] * t_paths[p];
        const float coef = tval / (wbuf[bin][p / NN] * inv_last);
        atomicAdd(&out[tid], wbuf[bin][tid] * inv_last * coef);
    }
}

extern "C" void kernel_launch(void* const* d_in, const int* in_sizes, int n_in,
                              void* d_out, int out_size) {
    // metadata order: 0:x (unused), 1:r_zeros, 2:r_const, 3:t_paths,
    //                 4:weights_t, 5:weights_r
    const float* r_zeros   = (const float*)d_in[1];
    const float* r_const   = (const float*)d_in[2];
    const float* t_paths   = (const float*)d_in[3];
    const float* weights_t = (const float*)d_in[4];
    const float* weights_r = (const float*)d_in[5];
    float* out = (float*)d_out;

    zero_out<<<1, NN>>>(out);
    power_iter_kernel<<<PAIRS, TPB>>>(r_zeros, r_const, t_paths, weights_t,
                                      weights_r, out);
}

// round 14
// speedup vs baseline: 1.2518x; 1.2518x over previous
#include <cuda_runtime.h>
#include <math.h>

#define NN 80
#define PAIRS (NN * NN)          // 6400
#define MAX_ITERS 60
#define TOL 1e-3f
#define TPB 256

__global__ void zero_out(float* __restrict__ out) {
    out[threadIdx.x] = 0.0f;     // d_out is poisoned; we accumulate atomically
}

__global__ __launch_bounds__(TPB, 4)
void power_iter_kernel(const float* __restrict__ r_zeros,
                       const float* __restrict__ r_const,
                       const float* __restrict__ t_paths,
                       const float* __restrict__ weights_t,
                       const float* __restrict__ weights_r,
                       float* __restrict__ out) {
    __shared__ float wbuf[2][NN];  // ping-pong: unnormalized w = A v
    __shared__ float red_ww[8];    // per-warp partials of w.w
    __shared__ float red_vw[8];    // per-warp partials of v.(Av)
    __shared__ float s_n2;         // broadcast: ||w_out||^2
    __shared__ float s_ev;         // broadcast: v_in . (A v_in)

    const int p    = blockIdx.x;
    const int tid  = threadIdx.x;
    const int warp = tid >> 5;
    const int lane = tid & 31;
    const bool hi  = (lane & 16) != 0;
    const float C0 = 0.11180339887498949f;  // 1/sqrt(80)

    // ---- Build A = weights_r * r_zeros + r_const DIRECTLY INTO REGISTERS.
    // Warp w owns rows {w, w+8, ..., w+72}. Lane holds cols lane, lane+32,
    // lane+64 (lane<16 only). Coalesced; streaming hint (read-once).
    // Since v0 = C0 * ones, A v0 = C0 * rowsum(A): accumulate per-lane row
    // partial sums during the build -> mv#0's FMAs and v-reads are free.
    const size_t base = (size_t)p * (NN * NN);
    const float* __restrict__ rz = r_zeros   + base;
    const float* __restrict__ rc = r_const   + base;
    const float* __restrict__ wr = weights_r + base;

    float a0[10], a1[10], a2[10], rs[10];
    #pragma unroll
    for (int r = 0; r < 10; ++r) {
        const int row = warp + (r << 3);
        const int o0  = row * NN + lane;
        const int o1  = o0 + 32;
        a0[r] = fmaf(__ldcs(wr + o0), __ldcs(rz + o0), __ldcs(rc + o0));
        a1[r] = fmaf(__ldcs(wr + o1), __ldcs(rz + o1), __ldcs(rc + o1));
        a2[r] = 0.0f;
        if (lane < 16) {
            const int o2 = o0 + 64;
            a2[r] = fmaf(__ldcs(wr + o2), __ldcs(rz + o2), __ldcs(rc + o2));
        }
        rs[r] = a0[r] + a1[r] + a2[r];   // per-lane partial rowsum
    }

    // ---- mv#0 fused: w0 = A v0 = C0*rowsum; s_n2 = w0.w0; s_ev = v0.w0.
    // Same pair-folded reduction as the hot mv (6 SHFL per 2 rows).
    {
        float ww = 0.0f, vwacc = 0.0f;
        #pragma unroll
        for (int k = 0; k < 5; ++k) {
            const int rA = warp + (k << 4);
            const int rB = rA + 8;
            float sA = rs[2*k];
            float sB = rs[2*k+1];
            sA += __shfl_xor_sync(0xFFFFFFFFu, sA, 16);
            sB += __shfl_xor_sync(0xFFFFFFFFu, sB, 16);
            float u = hi ? sB : sA;
            u += __shfl_xor_sync(0xFFFFFFFFu, u, 8);
            u += __shfl_xor_sync(0xFFFFFFFFu, u, 4);
            u += __shfl_xor_sync(0xFFFFFFFFu, u, 2);
            u += __shfl_xor_sync(0xFFFFFFFFu, u, 1);
            u *= C0;                              // w0[row]
            if ((lane & 15) == 0) {
                const int row = hi ? rB : rA;
                wbuf[1][row] = u;
                ww    = fmaf(u, u, ww);
                vwacc = fmaf(C0, u, vwacc);       // v0[row] = C0
            }
        }
        ww    += __shfl_xor_sync(0xFFFFFFFFu, ww,    16);
        vwacc += __shfl_xor_sync(0xFFFFFFFFu, vwacc, 16);
        if (lane == 0) { red_ww[warp] = ww; red_vw[warp] = vwacc; }
        __syncthreads();
        if (tid == 0) {
            float A = 0.0f, B = 0.0f;
            #pragma unroll
            for (int k = 0; k < 8; ++k) { A += red_ww[k]; B += red_vw[k]; }
            s_n2 = A; s_ev = B;
        }
        __syncthreads();
    }

    // mv: v_in = in*inv; out = A v_in; s_n2 = out.out; s_ev = v_in.out.
    // Pair-folded reduction (R10/R11-proven). IDENTICAL to R11 hot loop.
    auto mv = [&](const float* in, float* outb, float inv) {
        const float vr0 = in[lane] * inv;
        const float vr1 = in[lane + 32] * inv;
        const float vr2 = (lane < 16) ? in[lane + 64] * inv : 0.0f;
        float ww = 0.0f, vwacc = 0.0f;
        #pragma unroll
        for (int k = 0; k < 5; ++k) {
            const int rA = warp + (k << 4);       // row for r=2k
            const int rB = rA + 8;                // row for r=2k+1
            float sA = a0[2*k] * vr0;
            sA = fmaf(a1[2*k],   vr1, sA);
            sA = fmaf(a2[2*k],   vr2, sA);
            float sB = a0[2*k+1] * vr0;
            sB = fmaf(a1[2*k+1], vr1, sB);
            sB = fmaf(a2[2*k+1], vr2, sB);
            sA += __shfl_xor_sync(0xFFFFFFFFu, sA, 16);
            sB += __shfl_xor_sync(0xFFFFFFFFu, sB, 16);
            float u = hi ? sB : sA;               // 0-15: rowA, 16-31: rowB
            u += __shfl_xor_sync(0xFFFFFFFFu, u, 8);
            u += __shfl_xor_sync(0xFFFFFFFFu, u, 4);
            u += __shfl_xor_sync(0xFFFFFFFFu, u, 2);
            u += __shfl_xor_sync(0xFFFFFFFFu, u, 1);
            if ((lane & 15) == 0) {               // leaders: lane 0 & lane 16
                const int row = hi ? rB : rA;
                outb[row] = u;
                ww    = fmaf(u, u, ww);
                vwacc = fmaf(in[row] * inv, u, vwacc);
            }
        }
        ww    += __shfl_xor_sync(0xFFFFFFFFu, ww,    16);
        vwacc += __shfl_xor_sync(0xFFFFFFFFu, vwacc, 16);
        if (lane == 0) { red_ww[warp] = ww; red_vw[warp] = vwacc; }
        __syncthreads();
        if (tid == 0) {
            float A = 0.0f, B = 0.0f;
            #pragma unroll
            for (int k = 0; k < 8; ++k) { A += red_ww[k]; B += red_vw[k]; }
            s_n2 = A; s_ev = B;
        }
        __syncthreads();
    };

    float ev = s_ev;   // ev0 = v0.(A v0)

    // ---- iterate: v_{k+1} = w_k/||w_k||; ev_{k+1} = v_{k+1}.(A v_{k+1})
    int bin = 1;
    float inv_last = 1.0f;
    for (int it = 0; it < MAX_ITERS; ++it) {
        const float inv = 1.0f / sqrtf(s_n2);     // uniform per-thread scalar
        mv(wbuf[bin], wbuf[bin ^ 1], inv);        // reads w*inv, writes A v_new
        inv_last = inv;
        const float ev_new = s_ev;
        if (fabsf(ev - ev_new) < TOL) break;      // v_final = wbuf[bin]*inv
        ev = ev_new;
        bin ^= 1;
    }

    // ---- out[i] += v_final[i] * (T[p] / v_final[src]),  src = p / n
    if (tid < NN) {
        const float tval = weights_t[p] * t_paths[p];
        const float coef = tval / (wbuf[bin][p / NN] * inv_last);
        atomicAdd(&out[tid], wbuf[bin][tid] * inv_last * coef);
    }
}

extern "C" void kernel_launch(void* const* d_in, const int* in_sizes, int n_in,
                              void* d_out, int out_size) {
    // metadata order: 0:x (unused), 1:r_zeros, 2:r_const, 3:t_paths,
    //                 4:weights_t, 5:weights_r
    const float* r_zeros   = (const float*)d_in[1];
    const float* r_const   = (const float*)d_in[2];
    const float* t_paths   = (const float*)d_in[3];
    const float* weights_t = (const float*)d_in[4];
    const float* weights_r = (const float*)d_in[5];
    float* out = (float*)d_out;

    zero_out<<<1, NN>>>(out);
    power_iter_kernel<<<PAIRS, TPB>>>(r_zeros, r_const, t_paths, weights_t,
                                      weights_r, out);
}

// round 15
// speedup vs baseline: 1.3067x; 1.0438x over previous
#include <cuda_runtime.h>
#include <math.h>

#define NN 80
#define PAIRS (NN * NN)          // 6400
#define MAX_ITERS 60
#define TOL 1e-3f
#define TPB 256

__global__ void zero_out(float* __restrict__ out) {
    out[threadIdx.x] = 0.0f;     // d_out is poisoned; we accumulate atomically
}

__global__ __launch_bounds__(TPB, 4)
void power_iter_kernel(const float* __restrict__ r_zeros,
                       const float* __restrict__ r_const,
                       const float* __restrict__ t_paths,
                       const float* __restrict__ weights_t,
                       const float* __restrict__ weights_r,
                       float* __restrict__ out) {
    __shared__ float wbuf[2][NN];  // ping-pong: unnormalized w = A v
    __shared__ float red_ww[8];    // per-warp partials of w.w
    __shared__ float red_vw[8];    // per-warp partials of v.(Av)
    __shared__ float s_n2;         // broadcast: ||w_out||^2
    __shared__ float s_ev;         // broadcast: v_in . (A v_in)

    const int p    = blockIdx.x;
    const int tid  = threadIdx.x;
    const int warp = tid >> 5;
    const int lane = tid & 31;
    const bool hi  = (lane & 16) != 0;
    const float C0 = 0.11180339887498949f;  // 1/sqrt(80)

    // ---- Build A = weights_r * r_zeros + r_const into registers.
    // Warp w owns rows {w, w+8, ..., w+72}. Cols 0..63: lane holds (lane,
    // lane+32) for each of 10 rows (a0,a1). Cols 64..79 (tail): PACKED —
    // a2p[k] holds the tails of row-pair (warp+16k, warp+16k+8): lanes 0-15
    // carry rowA cols 64+lane, lanes 16-31 carry rowB cols 64+(lane-16).
    // This matches the pair-folded reduction's post-merge lane layout, so
    // the tail becomes a single FMA after the merge. All loads coalesced.
    const size_t base = (size_t)p * (NN * NN);
    const float* __restrict__ rz = r_zeros   + base;
    const float* __restrict__ rc = r_const   + base;
    const float* __restrict__ wr = weights_r + base;

    float a0[10], a1[10], rs[10], a2p[5];
    #pragma unroll
    for (int r = 0; r < 10; ++r) {
        const int row = warp + (r << 3);
        const int o0  = row * NN + lane;
        const int o1  = o0 + 32;
        a0[r] = fmaf(__ldcs(wr + o0), __ldcs(rz + o0), __ldcs(rc + o0));
        a1[r] = fmaf(__ldcs(wr + o1), __ldcs(rz + o1), __ldcs(rc + o1));
        rs[r] = a0[r] + a1[r];           // per-lane partial rowsum (cols 0-63)
    }
    #pragma unroll
    for (int k = 0; k < 5; ++k) {
        // reg k: lanes 0-15 -> row warp+16k, lanes 16-31 -> row warp+16k+8
        const int row = warp + (k << 4) + (hi ? 8 : 0);
        const int o2  = row * NN + 64 + (lane & 15);
        a2p[k] = fmaf(__ldcs(wr + o2), __ldcs(rz + o2), __ldcs(rc + o2));
    }

    // ---- mv#0 fused: w0 = A v0 = C0*rowsum; s_n2 = w0.w0; s_ev = v0.w0.
    {
        float ww = 0.0f, vwacc = 0.0f;
        #pragma unroll
        for (int k = 0; k < 5; ++k) {
            const int rA = warp + (k << 4);
            const int rB = rA + 8;
            float sA = rs[2*k];
            float sB = rs[2*k+1];
            sA += __shfl_xor_sync(0xFFFFFFFFu, sA, 16);
            sB += __shfl_xor_sync(0xFFFFFFFFu, sB, 16);
            float u = (hi ? sB : sA) + a2p[k];    // tail joins after merge
            u += __shfl_xor_sync(0xFFFFFFFFu, u, 8);
            u += __shfl_xor_sync(0xFFFFFFFFu, u, 4);
            u += __shfl_xor_sync(0xFFFFFFFFu, u, 2);
            u += __shfl_xor_sync(0xFFFFFFFFu, u, 1);
            u *= C0;                              // w0[row]
            if ((lane & 15) == 0) {
                const int row = hi ? rB : rA;
                wbuf[1][row] = u;
                ww    = fmaf(u, u, ww);
                vwacc = fmaf(C0, u, vwacc);       // v0[row] = C0
            }
        }
        ww    += __shfl_xor_sync(0xFFFFFFFFu, ww,    16);
        vwacc += __shfl_xor_sync(0xFFFFFFFFu, vwacc, 16);
        if (lane == 0) { red_ww[warp] = ww; red_vw[warp] = vwacc; }
        __syncthreads();
        if (tid == 0) {
            float A = 0.0f, B = 0.0f;
            #pragma unroll
            for (int k = 0; k < 8; ++k) { A += red_ww[k]; B += red_vw[k]; }
            s_n2 = A; s_ev = B;
        }
        __syncthreads();
    }

    // mv: v_in = in*inv; out = A v_in; s_n2 = out.out; s_ev = v_in.out.
    // Pair-folded reduction; packed tail adds ONE fma post-merge.
    auto mv = [&](const float* in, float* outb, float inv) {
        const float vr0 = in[lane] * inv;
        const float vr1 = in[lane + 32] * inv;
        const float vt  = in[64 + (lane & 15)] * inv;   // tail v, row-half split
        float ww = 0.0f, vwacc = 0.0f;
        #pragma unroll
        for (int k = 0; k < 5; ++k) {
            const int rA = warp + (k << 4);       // low-lane row
            const int rB = rA + 8;                // high-lane row
            float sA = a0[2*k] * vr0;
            sA = fmaf(a1[2*k],   vr1, sA);
            float sB = a0[2*k+1] * vr0;
            sB = fmaf(a1[2*k+1], vr1, sB);
            sA += __shfl_xor_sync(0xFFFFFFFFu, sA, 16);
            sB += __shfl_xor_sync(0xFFFFFFFFu, sB, 16);
            float u = hi ? sB : sA;               // 0-15: rowA, 16-31: rowB
            u = fmaf(a2p[k], vt, u);              // tail contribution
            u += __shfl_xor_sync(0xFFFFFFFFu, u, 8);
            u += __shfl_xor_sync(0xFFFFFFFFu, u, 4);
            u += __shfl_xor_sync(0xFFFFFFFFu, u, 2);
            u += __shfl_xor_sync(0xFFFFFFFFu, u, 1);
            if ((lane & 15) == 0) {               // leaders: lane 0 & lane 16
                const int row = hi ? rB : rA;
                outb[row] = u;
                ww    = fmaf(u, u, ww);
                vwacc = fmaf(in[row] * inv, u, vwacc);
            }
        }
        ww    += __shfl_xor_sync(0xFFFFFFFFu, ww,    16);
        vwacc += __shfl_xor_sync(0xFFFFFFFFu, vwacc, 16);
        if (lane == 0) { red_ww[warp] = ww; red_vw[warp] = vwacc; }
        __syncthreads();
        if (tid == 0) {
            float A = 0.0f, B = 0.0f;
            #pragma unroll
            for (int k = 0; k < 8; ++k) { A += red_ww[k]; B += red_vw[k]; }
            s_n2 = A; s_ev = B;
        }
        __syncthreads();
    };

    float ev = s_ev;   // ev0 = v0.(A v0)

    // ---- iterate: v_{k+1} = w_k/||w_k||; ev_{k+1} = v_{k+1}.(A v_{k+1})
    int bin = 1;
    float inv_last = 1.0f;
    for (int it = 0; it < MAX_ITERS; ++it) {
        const float inv = 1.0f / sqrtf(s_n2);     // uniform per-thread scalar
        mv(wbuf[bin], wbuf[bin ^ 1], inv);        // reads w*inv, writes A v_new
        inv_last = inv;
        const float ev_new = s_ev;
        if (fabsf(ev - ev_new) < TOL) break;      // v_final = wbuf[bin]*inv
        ev = ev_new;
        bin ^= 1;
    }

    // ---- out[i] += v_final[i] * (T[p] / v_final[src]),  src = p / n
    if (tid < NN) {
        const float tval = weights_t[p] * t_paths[p];
        const float coef = tval / (wbuf[bin][p / NN] * inv_last);
        atomicAdd(&out[tid], wbuf[bin][tid] * inv_last * coef);
    }
}

extern "C" void kernel_launch(void* const* d_in, const int* in_sizes, int n_in,
                              void* d_out, int out_size) {
    // metadata order: 0:x (unused), 1:r_zeros, 2:r_const, 3:t_paths,
    //                 4:weights_t, 5:weights_r
    const float* r_zeros   = (const float*)d_in[1];
    const float* r_const   = (const float*)d_in[2];
    const float* t_paths   = (const float*)d_in[3];
    const float* weights_t = (const float*)d_in[4];
    const float* weights_r = (const float*)d_in[5];
    float* out = (float*)d_out;

    zero_out<<<1, NN>>>(out);
    power_iter_kernel<<<PAIRS, TPB>>>(r_zeros, r_const, t_paths, weights_t,
                                      weights_r, out);
}

// round 16
// speedup vs baseline: 1.3082x; 1.0012x over previous
#include <cuda_runtime.h>
#include <math.h>

#define NN 80
#define PAIRS (NN * NN)          // 6400
#define MAX_ITERS 60
#define TOL 1e-3f
#define TPB 256

__global__ void zero_out(float* __restrict__ out) {
    out[threadIdx.x] = 0.0f;     // d_out is poisoned; we accumulate atomically
}

__global__ __launch_bounds__(TPB, 4)
void power_iter_kernel(const float* __restrict__ r_zeros,
                       const float* __restrict__ r_const,
                       const float* __restrict__ t_paths,
                       const float* __restrict__ weights_t,
                       const float* __restrict__ weights_r,
                       float* __restrict__ out) {
    __shared__ float wbuf[2][NN];  // ping-pong: unnormalized w = A v
    __shared__ float red_ww[8];    // per-warp partials of w.w
    __shared__ float red_vw[8];    // per-warp partials of v.(Av)
    __shared__ float s_n2;         // broadcast: ||w_out||^2
    __shared__ float s_ev;         // broadcast: v_in . (A v_in)

    const int p    = blockIdx.x;
    const int tid  = threadIdx.x;
    const int warp = tid >> 5;
    const int lane = tid & 31;
    const bool hi  = (lane & 16) != 0;
    const float C0 = 0.11180339887498949f;  // 1/sqrt(80)

    // ---- Build A = weights_r * r_zeros + r_const into registers (R15 layout).
    // Warp w owns rows {w, w+8, ..., w+72} (reg r <-> row w+8r). Cols 0..63:
    // lane holds (lane, lane+32). Tail cols 64..79 packed: a2p[k] = tails of
    // row-pair (reg 2k, reg 2k+1); lanes 0-15 rowA, lanes 16-31 rowB.
    const size_t base = (size_t)p * (NN * NN);
    const float* __restrict__ rz = r_zeros   + base;
    const float* __restrict__ rc = r_const   + base;
    const float* __restrict__ wr = weights_r + base;

    float a0[10], a1[10], rs[10], a2p[5];
    #pragma unroll
    for (int r = 0; r < 10; ++r) {
        const int row = warp + (r << 3);
        const int o0  = row * NN + lane;
        const int o1  = o0 + 32;
        a0[r] = fmaf(__ldcs(wr + o0), __ldcs(rz + o0), __ldcs(rc + o0));
        a1[r] = fmaf(__ldcs(wr + o1), __ldcs(rz + o1), __ldcs(rc + o1));
        rs[r] = a0[r] + a1[r];           // per-lane partial rowsum (cols 0-63)
    }
    #pragma unroll
    for (int k = 0; k < 5; ++k) {
        const int row = warp + (k << 4) + (hi ? 8 : 0);
        const int o2  = row * NN + 64 + (lane & 15);
        a2p[k] = fmaf(__ldcs(wr + o2), __ldcs(rz + o2), __ldcs(rc + o2));
    }

    // ---- mv#0 fused (R15-proven pair version): w0 = C0*rowsum(A).
    {
        float ww = 0.0f, vwacc = 0.0f;
        #pragma unroll
        for (int k = 0; k < 5; ++k) {
            const int rA = warp + (k << 4);
            const int rB = rA + 8;
            float sA = rs[2*k];
            float sB = rs[2*k+1];
            sA += __shfl_xor_sync(0xFFFFFFFFu, sA, 16);
            sB += __shfl_xor_sync(0xFFFFFFFFu, sB, 16);
            float u = (hi ? sB : sA) + a2p[k];
            u += __shfl_xor_sync(0xFFFFFFFFu, u, 8);
            u += __shfl_xor_sync(0xFFFFFFFFu, u, 4);
            u += __shfl_xor_sync(0xFFFFFFFFu, u, 2);
            u += __shfl_xor_sync(0xFFFFFFFFu, u, 1);
            u *= C0;
            if ((lane & 15) == 0) {
                const int row = hi ? rB : rA;
                wbuf[1][row] = u;
                ww    = fmaf(u, u, ww);
                vwacc = fmaf(C0, u, vwacc);
            }
        }
        ww    += __shfl_xor_sync(0xFFFFFFFFu, ww,    16);
        vwacc += __shfl_xor_sync(0xFFFFFFFFu, vwacc, 16);
        if (lane == 0) { red_ww[warp] = ww; red_vw[warp] = vwacc; }
        __syncthreads();
        if (tid == 0) {
            float A = 0.0f, B = 0.0f;
            #pragma unroll
            for (int k = 0; k < 8; ++k) { A += red_ww[k]; B += red_vw[k]; }
            s_n2 = A; s_ev = B;
        }
        __syncthreads();
    }

    // mv (QUAD-FOLD): rows in groups of 4 share the last 3 fold stages.
    // Quad q covers regs 4q..4q+3: prefold xor16 (x4), merge pairs + tail
    // FMA, xor8 (x2), merge on bit-3, xor4/2/1 shared. Leaders lanes
    // {0,8,16,24} -> rows 4q + {0,2,1,3}. Remaining pair (regs 8,9) as R15.
    auto mv = [&](const float* in, float* outb, float inv) {
        const float vr0 = in[lane] * inv;
        const float vr1 = in[lane + 32] * inv;
        const float vt  = in[64 + (lane & 15)] * inv;
        float ww = 0.0f, vwacc = 0.0f;
        #pragma unroll
        for (int q = 0; q < 2; ++q) {
            const int r0 = 4*q;
            float s0 = fmaf(a1[r0],   vr1, a0[r0]   * vr0);
            float s1 = fmaf(a1[r0+1], vr1, a0[r0+1] * vr0);
            float s2 = fmaf(a1[r0+2], vr1, a0[r0+2] * vr0);
            float s3 = fmaf(a1[r0+3], vr1, a0[r0+3] * vr0);
            s0 += __shfl_xor_sync(0xFFFFFFFFu, s0, 16);
            s1 += __shfl_xor_sync(0xFFFFFFFFu, s1, 16);
            s2 += __shfl_xor_sync(0xFFFFFFFFu, s2, 16);
            s3 += __shfl_xor_sync(0xFFFFFFFFu, s3, 16);
            float uA = hi ? s1 : s0;            // lanes 0-15: r0, 16-31: r1
            uA = fmaf(a2p[2*q], vt, uA);        // tails of (r0, r1)
            float uB = hi ? s3 : s2;            // lanes 0-15: r2, 16-31: r3
            uB = fmaf(a2p[2*q+1], vt, uB);      // tails of (r2, r3)
            uA += __shfl_xor_sync(0xFFFFFFFFu, uA, 8);
            uB += __shfl_xor_sync(0xFFFFFFFFu, uB, 8);
            float u = (lane & 8) ? uB : uA;     // 8-lane groups: r0,r2,r1,r3
            u += __shfl_xor_sync(0xFFFFFFFFu, u, 4);
            u += __shfl_xor_sync(0xFFFFFFFFu, u, 2);
            u += __shfl_xor_sync(0xFFFFFFFFu, u, 1);
            if ((lane & 7) == 0) {
                const int ridx = 4*q + (((lane >> 3) & 1) << 1)
                                      + ((lane >> 4) & 1);
                const int row = warp + (ridx << 3);
                outb[row] = u;
                ww    = fmaf(u, u, ww);
                vwacc = fmaf(in[row] * inv, u, vwacc);
            }
        }
        {   // pair: regs 8,9 (rows w+64, w+72), tail a2p[4]
            float sA = fmaf(a1[8], vr1, a0[8] * vr0);
            float sB = fmaf(a1[9], vr1, a0[9] * vr0);
            sA += __shfl_xor_sync(0xFFFFFFFFu, sA, 16);
            sB += __shfl_xor_sync(0xFFFFFFFFu, sB, 16);
            float u = hi ? sB : sA;
            u = fmaf(a2p[4], vt, u);
            u += __shfl_xor_sync(0xFFFFFFFFu, u, 8);
            u += __shfl_xor_sync(0xFFFFFFFFu, u, 4);
            u += __shfl_xor_sync(0xFFFFFFFFu, u, 2);
            u += __shfl_xor_sync(0xFFFFFFFFu, u, 1);
            if ((lane & 15) == 0) {
                const int row = warp + ((hi ? 9 : 8) << 3);
                outb[row] = u;
                ww    = fmaf(u, u, ww);
                vwacc = fmaf(in[row] * inv, u, vwacc);
            }
        }
        // fold leader accumulators (lanes 0,8,16,24 -> lane 0)
        ww    += __shfl_xor_sync(0xFFFFFFFFu, ww,    8);
        ww    += __shfl_xor_sync(0xFFFFFFFFu, ww,    16);
        vwacc += __shfl_xor_sync(0xFFFFFFFFu, vwacc, 8);
        vwacc += __shfl_xor_sync(0xFFFFFFFFu, vwacc, 16);
        if (lane == 0) { red_ww[warp] = ww; red_vw[warp] = vwacc; }
        __syncthreads();
        if (tid == 0) {
            float A = 0.0f, B = 0.0f;
            #pragma unroll
            for (int k = 0; k < 8; ++k) { A += red_ww[k]; B += red_vw[k]; }
            s_n2 = A; s_ev = B;
        }
        __syncthreads();
    };

    float ev = s_ev;   // ev0 = v0.(A v0)

    // ---- iterate: v_{k+1} = w_k/||w_k||; ev_{k+1} = v_{k+1}.(A v_{k+1})
    int bin = 1;
    float inv_last = 1.0f;
    for (int it = 0; it < MAX_ITERS; ++it) {
        const float inv = 1.0f / sqrtf(s_n2);     // uniform per-thread scalar
        mv(wbuf[bin], wbuf[bin ^ 1], inv);        // reads w*inv, writes A v_new
        inv_last = inv;
        const float ev_new = s_ev;
        if (fabsf(ev - ev_new) < TOL) break;      // v_final = wbuf[bin]*inv
        ev = ev_new;
        bin ^= 1;
    }

    // ---- out[i] += v_final[i] * (T[p] / v_final[src]),  src = p / n
    if (tid < NN) {
        const float tval = weights_t[p] * t_paths[p];
        const float coef = tval / (wbuf[bin][p / NN] * inv_last);
        atomicAdd(&out[tid], wbuf[bin][tid] * inv_last * coef);
    }
}

extern "C" void kernel_launch(void* const* d_in, const int* in_sizes, int n_in,
                              void* d_out, int out_size) {
    // metadata order: 0:x (unused), 1:r_zeros, 2:r_const, 3:t_paths,
    //                 4:weights_t, 5:weights_r
    const float* r_zeros   = (const float*)d_in[1];
    const float* r_const   = (const float*)d_in[2];
    const float* t_paths   = (const float*)d_in[3];
    const float* weights_t = (const float*)d_in[4];
    const float* weights_r = (const float*)d_in[5];
    float* out = (float*)d_out;

    zero_out<<<1, NN>>>(out);
    power_iter_kernel<<<PAIRS, TPB>>>(r_zeros, r_const, t_paths, weights_t,
                                      weights_r, out);
}